// round 1
// baseline (speedup 1.0000x reference)
#include <cuda_runtime.h>

#define SEQ 2048
#define DE  1024
#define NH  16
#define DH  64

// Scratch (device globals — no allocation allowed in kernel_launch).
__device__ float g_q[NH * SEQ * DH];
__device__ float g_k[NH * SEQ * DH];
__device__ float g_v[NH * SEQ * DH];
__device__ float g_z[NH * SEQ * DH];

// ---------------------------------------------------------------------------
// Kernel 1: QKV projection.
//   q[a,c,h] = sum_e W_Q[a,h,e] * x[c,e]   (same for k, v)
// One 64x64 output tile per block; BK=32; 256 threads, 4x4 microtile each.
// grid = (1, SEQ/64, 48): z selects {Q,K,V} x head.
// ---------------------------------------------------------------------------
__global__ __launch_bounds__(256) void qkv_kernel(
    const float* __restrict__ x,  const float* __restrict__ wq,
    const float* __restrict__ wk, const float* __restrict__ wv)
{
    __shared__ float As[64][33];
    __shared__ float Bs[64][33];

    const int mat  = blockIdx.z >> 4;   // 0=Q, 1=K, 2=V
    const int head = blockIdx.z & 15;
    const float* W = (mat == 0 ? wq : (mat == 1 ? wk : wv)) + (size_t)head * DH * DE;
    float*       O = (mat == 0 ? g_q : (mat == 1 ? g_k : g_v)) + (size_t)head * SEQ * DH;

    const int c0 = blockIdx.y * 64;
    const int tx = threadIdx.x, ty = threadIdx.y;
    const int t  = ty * 16 + tx;

    float acc[4][4] = {};

    for (int k0 = 0; k0 < DE; k0 += 32) {
        #pragma unroll
        for (int i = 0; i < 2; i++) {
            int f = t + 256 * i;
            int row = f >> 3, quad = f & 7;
            float4 av = *(const float4*)(x + (size_t)(c0 + row) * DE + k0 + quad * 4);
            As[row][quad*4+0] = av.x; As[row][quad*4+1] = av.y;
            As[row][quad*4+2] = av.z; As[row][quad*4+3] = av.w;
            float4 bv = *(const float4*)(W + (size_t)row * DE + k0 + quad * 4);
            Bs[row][quad*4+0] = bv.x; Bs[row][quad*4+1] = bv.y;
            Bs[row][quad*4+2] = bv.z; Bs[row][quad*4+3] = bv.w;
        }
        __syncthreads();

        #pragma unroll
        for (int kk = 0; kk < 32; kk++) {
            float a[4], b[4];
            #pragma unroll
            for (int i = 0; i < 4; i++) a[i] = As[ty*4 + i][kk];
            #pragma unroll
            for (int j = 0; j < 4; j++) b[j] = Bs[tx*4 + j][kk];
            #pragma unroll
            for (int i = 0; i < 4; i++)
                #pragma unroll
                for (int j = 0; j < 4; j++)
                    acc[i][j] = fmaf(a[i], b[j], acc[i][j]);
        }
        __syncthreads();
    }

    #pragma unroll
    for (int i = 0; i < 4; i++)
        #pragma unroll
        for (int j = 0; j < 4; j++)
            O[(size_t)(c0 + ty*4 + i) * DH + tx*4 + j] = acc[i][j];
}

// ---------------------------------------------------------------------------
// Kernel 2: fused causal flash attention.
// NOTE the reference einsum swaps roles: scores[c,C] = k_c . q_C, so the
// "row" operand is K and the "key/value" stream is (Q, V).
//   z[c,:] = softmax_C( mask(k_c . q_C) / 8 ) @ V
// One block = (head, 64-row tile). Online softmax, all fp32.
// Dynamic smem: Kb/Qt/Vt/Ps, each 64x65 floats (65 KB total).
// ---------------------------------------------------------------------------
__global__ __launch_bounds__(256) void flash_kernel()
{
    extern __shared__ float sm[];
    float* Kb = sm;                  // [64][65]  rows (k)
    float* Qt = sm + 64 * 65;        // [64][65]  key tile (q)
    float* Vt = sm + 2 * 64 * 65;    // [64][65]  value tile
    float* Ps = sm + 3 * 64 * 65;    // [64][65]  probabilities

    const int head = blockIdx.y;
    const int c0b  = blockIdx.x * 64;
    const float* Kh = g_k + (size_t)head * SEQ * DH;
    const float* Qh = g_q + (size_t)head * SEQ * DH;
    const float* Vh = g_v + (size_t)head * SEQ * DH;

    const int tx = threadIdx.x, ty = threadIdx.y;
    const int t  = ty * 16 + tx;
    const float SC = 0.125f;  // 1/sqrt(64)

    // Load this block's 64 K-rows once.
    #pragma unroll
    for (int i = 0; i < 4; i++) {
        int f = t + 256 * i;
        int row = f >> 4, quad = f & 15;
        float4 v = *(const float4*)(Kh + (size_t)(c0b + row) * DH + quad * 4);
        float* p = Kb + row * 65 + quad * 4;
        p[0] = v.x; p[1] = v.y; p[2] = v.z; p[3] = v.w;
    }

    float accum[4][4] = {};
    float mrow[4], lrow[4];
    #pragma unroll
    for (int i = 0; i < 4; i++) { mrow[i] = -1e30f; lrow[i] = 0.0f; }

    for (int tt = 0; tt <= (int)blockIdx.x; tt++) {
        const int t0 = tt * 64;
        __syncthreads();  // previous iteration done with Qt/Vt/Ps (and Kb stores visible at tt=0)

        #pragma unroll
        for (int i = 0; i < 4; i++) {
            int f = t + 256 * i;
            int row = f >> 4, quad = f & 15;
            float4 qv = *(const float4*)(Qh + (size_t)(t0 + row) * DH + quad * 4);
            float* pq = Qt + row * 65 + quad * 4;
            pq[0] = qv.x; pq[1] = qv.y; pq[2] = qv.z; pq[3] = qv.w;
            float4 vv = *(const float4*)(Vh + (size_t)(t0 + row) * DH + quad * 4);
            float* pv = Vt + row * 65 + quad * 4;
            pv[0] = vv.x; pv[1] = vv.y; pv[2] = vv.z; pv[3] = vv.w;
        }
        __syncthreads();

        // S = K_rows @ Qt^T  (64x64 tile, 4x4 per thread)
        float s[4][4] = {};
        #pragma unroll 8
        for (int h = 0; h < DH; h++) {
            float a[4], b[4];
            #pragma unroll
            for (int i = 0; i < 4; i++) a[i] = Kb[(ty*4 + i) * 65 + h];
            #pragma unroll
            for (int j = 0; j < 4; j++) b[j] = Qt[(tx*4 + j) * 65 + h];
            #pragma unroll
            for (int i = 0; i < 4; i++)
                #pragma unroll
                for (int j = 0; j < 4; j++)
                    s[i][j] = fmaf(a[i], b[j], s[i][j]);
        }

        // Causal mask: keep col <= row.
        #pragma unroll
        for (int i = 0; i < 4; i++) {
            int gr = c0b + ty*4 + i;
            #pragma unroll
            for (int j = 0; j < 4; j++) {
                int gc = t0 + tx*4 + j;
                if (gc > gr) s[i][j] = -1e30f;
            }
        }

        // Online softmax update (row reductions across the 16 tx lanes).
        #pragma unroll
        for (int i = 0; i < 4; i++) {
            float mx = fmaxf(fmaxf(s[i][0], s[i][1]), fmaxf(s[i][2], s[i][3]));
            #pragma unroll
            for (int o = 1; o < 16; o <<= 1)
                mx = fmaxf(mx, __shfl_xor_sync(0xffffffffu, mx, o));
            float mnew = fmaxf(mrow[i], mx);
            float corr = __expf((mrow[i] - mnew) * SC);
            float rs = 0.0f;
            #pragma unroll
            for (int j = 0; j < 4; j++) {
                float p = __expf((s[i][j] - mnew) * SC);
                s[i][j] = p;
                rs += p;
            }
            #pragma unroll
            for (int o = 1; o < 16; o <<= 1)
                rs += __shfl_xor_sync(0xffffffffu, rs, o);
            lrow[i] = lrow[i] * corr + rs;
            mrow[i] = mnew;
            #pragma unroll
            for (int j = 0; j < 4; j++) accum[i][j] *= corr;
        }

        // Share P tile, then accumulate O += P @ V.
        #pragma unroll
        for (int i = 0; i < 4; i++)
            #pragma unroll
            for (int j = 0; j < 4; j++)
                Ps[(ty*4 + i) * 65 + tx*4 + j] = s[i][j];
        __syncthreads();

        #pragma unroll 4
        for (int c = 0; c < 64; c++) {
            float pr[4], vv[4];
            #pragma unroll
            for (int i = 0; i < 4; i++) pr[i] = Ps[(ty*4 + i) * 65 + c];
            #pragma unroll
            for (int j = 0; j < 4; j++) vv[j] = Vt[c * 65 + tx*4 + j];
            #pragma unroll
            for (int i = 0; i < 4; i++)
                #pragma unroll
                for (int j = 0; j < 4; j++)
                    accum[i][j] = fmaf(pr[i], vv[j], accum[i][j]);
        }
    }

    float* Zh = g_z + (size_t)head * SEQ * DH;
    #pragma unroll
    for (int i = 0; i < 4; i++) {
        float inv = 1.0f / lrow[i];
        #pragma unroll
        for (int j = 0; j < 4; j++)
            Zh[(size_t)(c0b + ty*4 + i) * DH + tx*4 + j] = accum[i][j] * inv;
    }
}

// ---------------------------------------------------------------------------
// Kernel 3: output projection.
//   out[c,e] = sum_{a,h} W_O[a,e,h] * z[a,c,h]
// Flattened K = a*64+h (1024). A[c,k] = z[a][c][h], B[e,k] = W_O[a][e][h].
// grid = (DE/64, SEQ/64).
// ---------------------------------------------------------------------------
__global__ __launch_bounds__(256) void oproj_kernel(
    const float* __restrict__ wo, float* __restrict__ out)
{
    __shared__ float As[64][33];
    __shared__ float Bs[64][33];

    const int e0 = blockIdx.x * 64;
    const int c0 = blockIdx.y * 64;
    const int tx = threadIdx.x, ty = threadIdx.y;
    const int t  = ty * 16 + tx;

    float acc[4][4] = {};

    for (int k0 = 0; k0 < NH * DH; k0 += 32) {
        #pragma unroll
        for (int i = 0; i < 2; i++) {
            int f = t + 256 * i;
            int row = f >> 3, quad = f & 7;
            int k = k0 + quad * 4;       // 4 contiguous k stay within one head (h % 16 <= 12)
            int a = k >> 6, h = k & 63;
            float4 av = *(const float4*)(g_z + (size_t)a * SEQ * DH + (size_t)(c0 + row) * DH + h);
            As[row][quad*4+0] = av.x; As[row][quad*4+1] = av.y;
            As[row][quad*4+2] = av.z; As[row][quad*4+3] = av.w;
            float4 bv = *(const float4*)(wo + (size_t)a * DE * DH + (size_t)(e0 + row) * DH + h);
            Bs[row][quad*4+0] = bv.x; Bs[row][quad*4+1] = bv.y;
            Bs[row][quad*4+2] = bv.z; Bs[row][quad*4+3] = bv.w;
        }
        __syncthreads();

        #pragma unroll
        for (int kk = 0; kk < 32; kk++) {
            float a[4], b[4];
            #pragma unroll
            for (int i = 0; i < 4; i++) a[i] = As[ty*4 + i][kk];
            #pragma unroll
            for (int j = 0; j < 4; j++) b[j] = Bs[tx*4 + j][kk];
            #pragma unroll
            for (int i = 0; i < 4; i++)
                #pragma unroll
                for (int j = 0; j < 4; j++)
                    acc[i][j] = fmaf(a[i], b[j], acc[i][j]);
        }
        __syncthreads();
    }

    #pragma unroll
    for (int i = 0; i < 4; i++)
        #pragma unroll
        for (int j = 0; j < 4; j++)
            out[(size_t)(c0 + ty*4 + i) * DE + e0 + tx*4 + j] = acc[i][j];
}

// ---------------------------------------------------------------------------
extern "C" void kernel_launch(void* const* d_in, const int* in_sizes, int n_in,
                              void* d_out, int out_size)
{
    const float* x  = (const float*)d_in[0];
    const float* wq = (const float*)d_in[1];
    const float* wk = (const float*)d_in[2];
    const float* wv = (const float*)d_in[3];
    const float* wo = (const float*)d_in[4];
    float* out = (float*)d_out;

    dim3 blk(16, 16);

    qkv_kernel<<<dim3(1, SEQ / 64, 48), blk>>>(x, wq, wk, wv);

    const size_t shm = 4 * 64 * 65 * sizeof(float);  // 66560 B
    cudaFuncSetAttribute(flash_kernel, cudaFuncAttributeMaxDynamicSharedMemorySize, (int)shm);
    flash_kernel<<<dim3(SEQ / 64, NH), blk, shm>>>();

    oproj_kernel<<<dim3(DE / 64, SEQ / 64), blk>>>(wo, out);
}

// round 8
// speedup vs baseline: 1.0698x; 1.0698x over previous
#include <cuda_runtime.h>

#define SEQ 2048
#define DE  1024
#define NH  16
#define DH  64

// Scratch (device globals — no allocation allowed in kernel_launch).
__device__ float g_q[NH * SEQ * DH];
__device__ float g_k[NH * SEQ * DH];
__device__ float g_v[NH * SEQ * DH];
__device__ float g_z[NH * SEQ * DH];

// ---------------------------------------------------------------------------
// Kernel 1: QKV projection (R1-proven, 97% of FFMA roofline).
//   q[a,c,h] = sum_e W_Q[a,h,e] * x[c,e]   (same for k, v)
// One 64x64 output tile per block; BK=32; 256 threads, 4x4 microtile each.
// grid = (1, SEQ/64, 48): z selects {Q,K,V} x head.
// ---------------------------------------------------------------------------
__global__ __launch_bounds__(256) void qkv_kernel(
    const float* __restrict__ x,  const float* __restrict__ wq,
    const float* __restrict__ wk, const float* __restrict__ wv)
{
    __shared__ float As[64][33];
    __shared__ float Bs[64][33];

    const int mat  = blockIdx.z >> 4;   // 0=Q, 1=K, 2=V
    const int head = blockIdx.z & 15;
    const float* W = (mat == 0 ? wq : (mat == 1 ? wk : wv)) + (size_t)head * DH * DE;
    float*       O = (mat == 0 ? g_q : (mat == 1 ? g_k : g_v)) + (size_t)head * SEQ * DH;

    const int c0 = blockIdx.y * 64;
    const int tx = threadIdx.x, ty = threadIdx.y;
    const int t  = ty * 16 + tx;

    float acc[4][4] = {};

    for (int k0 = 0; k0 < DE; k0 += 32) {
        #pragma unroll
        for (int i = 0; i < 2; i++) {
            int f = t + 256 * i;
            int row = f >> 3, quad = f & 7;
            float4 av = *(const float4*)(x + (size_t)(c0 + row) * DE + k0 + quad * 4);
            As[row][quad*4+0] = av.x; As[row][quad*4+1] = av.y;
            As[row][quad*4+2] = av.z; As[row][quad*4+3] = av.w;
            float4 bv = *(const float4*)(W + (size_t)row * DE + k0 + quad * 4);
            Bs[row][quad*4+0] = bv.x; Bs[row][quad*4+1] = bv.y;
            Bs[row][quad*4+2] = bv.z; Bs[row][quad*4+3] = bv.w;
        }
        __syncthreads();

        #pragma unroll
        for (int kk = 0; kk < 32; kk++) {
            float a[4], b[4];
            #pragma unroll
            for (int i = 0; i < 4; i++) a[i] = As[ty*4 + i][kk];
            #pragma unroll
            for (int j = 0; j < 4; j++) b[j] = Bs[tx*4 + j][kk];
            #pragma unroll
            for (int i = 0; i < 4; i++)
                #pragma unroll
                for (int j = 0; j < 4; j++)
                    acc[i][j] = fmaf(a[i], b[j], acc[i][j]);
        }
        __syncthreads();
    }

    #pragma unroll
    for (int i = 0; i < 4; i++)
        #pragma unroll
        for (int j = 0; j < 4; j++)
            O[(size_t)(c0 + ty*4 + i) * DH + tx*4 + j] = acc[i][j];
}

// ---------------------------------------------------------------------------
// Kernel 2: fused causal flash attention (R1 math; vectorized smem reads).
// scores[c,C] = k_c . q_C  (K rows, Q keys); mask C<=c; scale 1/8 after mask.
// Changes vs R1:
//   * K and Q tiles stored TRANSPOSED [h][row], stride 68 -> QK operand
//     reads are one LDS.128 each (was 8 scalar LDS per k-step).
//   * V tile [c][h] stride 68 -> PV vv read is LDS.128.
//   * longest-first block order: rt = gridDim.x-1-blockIdx.x.
// ---------------------------------------------------------------------------
#define FST 68   // smem stride (floats): 16B-aligned float4 rows, conflict-free

__global__ __launch_bounds__(256) void flash_kernel()
{
    extern __shared__ float sm[];
    float* KbT = sm;               // [64][FST] : [h][krow]
    float* QtT = sm + 64 * FST;    // [h][qrow]
    float* Vt  = sm + 2 * 64 * FST;// [c][h]
    float* Ps  = sm + 3 * 64 * FST;// [krow][c]

    const int head = blockIdx.y;
    const int rt   = (int)gridDim.x - 1 - (int)blockIdx.x;  // longest first
    const int c0b  = rt * 64;
    const float* Kh = g_k + (size_t)head * SEQ * DH;
    const float* Qh = g_q + (size_t)head * SEQ * DH;
    const float* Vh = g_v + (size_t)head * SEQ * DH;

    const int tx = threadIdx.x, ty = threadIdx.y;
    const int t  = ty * 16 + tx;
    const float SC = 0.125f;  // 1/sqrt(64)

    // Load this block's 64 K-rows once, transposed.
    #pragma unroll
    for (int i = 0; i < 4; i++) {
        int f = t + 256 * i;
        int row = f >> 4, quad = f & 15;
        float4 v = *(const float4*)(Kh + (size_t)(c0b + row) * DH + quad * 4);
        KbT[(quad*4 + 0) * FST + row] = v.x;
        KbT[(quad*4 + 1) * FST + row] = v.y;
        KbT[(quad*4 + 2) * FST + row] = v.z;
        KbT[(quad*4 + 3) * FST + row] = v.w;
    }

    float accum[4][4] = {};
    float mrow[4], lrow[4];
    #pragma unroll
    for (int i = 0; i < 4; i++) { mrow[i] = -1e30f; lrow[i] = 0.0f; }

    for (int tt = 0; tt <= rt; tt++) {
        const int t0 = tt * 64;
        __syncthreads();  // previous iter done with QtT/Vt/Ps (KbT visible at tt=0)

        #pragma unroll
        for (int i = 0; i < 4; i++) {
            int f = t + 256 * i;
            int row = f >> 4, quad = f & 15;
            float4 qv = *(const float4*)(Qh + (size_t)(t0 + row) * DH + quad * 4);
            QtT[(quad*4 + 0) * FST + row] = qv.x;
            QtT[(quad*4 + 1) * FST + row] = qv.y;
            QtT[(quad*4 + 2) * FST + row] = qv.z;
            QtT[(quad*4 + 3) * FST + row] = qv.w;
            float4 vv = *(const float4*)(Vh + (size_t)(t0 + row) * DH + quad * 4);
            *(float4*)(Vt + row * FST + quad * 4) = vv;
        }
        __syncthreads();

        // S = K_rows @ Qt^T : vectorized operand reads.
        float s[4][4] = {};
        #pragma unroll 8
        for (int h = 0; h < DH; h++) {
            float4 a4 = *(const float4*)(KbT + h * FST + ty * 4);
            float4 b4 = *(const float4*)(QtT + h * FST + tx * 4);
            float a[4] = { a4.x, a4.y, a4.z, a4.w };
            float b[4] = { b4.x, b4.y, b4.z, b4.w };
            #pragma unroll
            for (int i = 0; i < 4; i++)
                #pragma unroll
                for (int j = 0; j < 4; j++)
                    s[i][j] = fmaf(a[i], b[j], s[i][j]);
        }

        // Causal mask: keep col <= row.
        #pragma unroll
        for (int i = 0; i < 4; i++) {
            int gr = c0b + ty*4 + i;
            #pragma unroll
            for (int j = 0; j < 4; j++) {
                int gc = t0 + tx*4 + j;
                if (gc > gr) s[i][j] = -1e30f;
            }
        }

        // Online softmax update (row reductions across the 16 tx lanes).
        #pragma unroll
        for (int i = 0; i < 4; i++) {
            float mx = fmaxf(fmaxf(s[i][0], s[i][1]), fmaxf(s[i][2], s[i][3]));
            #pragma unroll
            for (int o = 1; o < 16; o <<= 1)
                mx = fmaxf(mx, __shfl_xor_sync(0xffffffffu, mx, o));
            float mnew = fmaxf(mrow[i], mx);
            float corr = __expf((mrow[i] - mnew) * SC);
            float rs = 0.0f;
            #pragma unroll
            for (int j = 0; j < 4; j++) {
                float p = __expf((s[i][j] - mnew) * SC);
                s[i][j] = p;
                rs += p;
            }
            #pragma unroll
            for (int o = 1; o < 16; o <<= 1)
                rs += __shfl_xor_sync(0xffffffffu, rs, o);
            lrow[i] = lrow[i] * corr + rs;
            mrow[i] = mnew;
            #pragma unroll
            for (int j = 0; j < 4; j++) accum[i][j] *= corr;
        }

        // Share P tile, then accumulate O += P @ V.
        #pragma unroll
        for (int i = 0; i < 4; i++)
            #pragma unroll
            for (int j = 0; j < 4; j++)
                Ps[(ty*4 + i) * FST + tx*4 + j] = s[i][j];
        __syncthreads();

        #pragma unroll 4
        for (int c = 0; c < 64; c++) {
            float pr[4];
            #pragma unroll
            for (int i = 0; i < 4; i++) pr[i] = Ps[(ty*4 + i) * FST + c];
            float4 v4 = *(const float4*)(Vt + c * FST + tx * 4);
            float vv[4] = { v4.x, v4.y, v4.z, v4.w };
            #pragma unroll
            for (int i = 0; i < 4; i++)
                #pragma unroll
                for (int j = 0; j < 4; j++)
                    accum[i][j] = fmaf(pr[i], vv[j], accum[i][j]);
        }
    }

    float* Zh = g_z + (size_t)head * SEQ * DH;
    #pragma unroll
    for (int i = 0; i < 4; i++) {
        float inv = 1.0f / lrow[i];
        #pragma unroll
        for (int j = 0; j < 4; j++)
            Zh[(size_t)(c0b + ty*4 + i) * DH + tx*4 + j] = accum[i][j] * inv;
    }
}

// ---------------------------------------------------------------------------
// Kernel 3: output projection (R1-proven).
//   out[c,e] = sum_{a,h} W_O[a,e,h] * z[a,c,h]
// Flattened K = a*64+h (1024). A[c,k] = z[a][c][h], B[e,k] = W_O[a][e][h].
// grid = (DE/64, SEQ/64).
// ---------------------------------------------------------------------------
__global__ __launch_bounds__(256) void oproj_kernel(
    const float* __restrict__ wo, float* __restrict__ out)
{
    __shared__ float As[64][33];
    __shared__ float Bs[64][33];

    const int e0 = blockIdx.x * 64;
    const int c0 = blockIdx.y * 64;
    const int tx = threadIdx.x, ty = threadIdx.y;
    const int t  = ty * 16 + tx;

    float acc[4][4] = {};

    for (int k0 = 0; k0 < NH * DH; k0 += 32) {
        #pragma unroll
        for (int i = 0; i < 2; i++) {
            int f = t + 256 * i;
            int row = f >> 3, quad = f & 7;
            int k = k0 + quad * 4;       // 4 contiguous k stay within one head
            int a = k >> 6, h = k & 63;
            float4 av = *(const float4*)(g_z + (size_t)a * SEQ * DH + (size_t)(c0 + row) * DH + h);
            As[row][quad*4+0] = av.x; As[row][quad*4+1] = av.y;
            As[row][quad*4+2] = av.z; As[row][quad*4+3] = av.w;
            float4 bv = *(const float4*)(wo + (size_t)a * DE * DH + (size_t)(e0 + row) * DH + h);
            Bs[row][quad*4+0] = bv.x; Bs[row][quad*4+1] = bv.y;
            Bs[row][quad*4+2] = bv.z; Bs[row][quad*4+3] = bv.w;
        }
        __syncthreads();

        #pragma unroll
        for (int kk = 0; kk < 32; kk++) {
            float a[4], b[4];
            #pragma unroll
            for (int i = 0; i < 4; i++) a[i] = As[ty*4 + i][kk];
            #pragma unroll
            for (int j = 0; j < 4; j++) b[j] = Bs[tx*4 + j][kk];
            #pragma unroll
            for (int i = 0; i < 4; i++)
                #pragma unroll
                for (int j = 0; j < 4; j++)
                    acc[i][j] = fmaf(a[i], b[j], acc[i][j]);
        }
        __syncthreads();
    }

    #pragma unroll
    for (int i = 0; i < 4; i++)
        #pragma unroll
        for (int j = 0; j < 4; j++)
            out[(size_t)(c0 + ty*4 + i) * DE + e0 + tx*4 + j] = acc[i][j];
}

// ---------------------------------------------------------------------------
extern "C" void kernel_launch(void* const* d_in, const int* in_sizes, int n_in,
                              void* d_out, int out_size)
{
    const float* x  = (const float*)d_in[0];
    const float* wq = (const float*)d_in[1];
    const float* wk = (const float*)d_in[2];
    const float* wv = (const float*)d_in[3];
    const float* wo = (const float*)d_in[4];
    float* out = (float*)d_out;

    dim3 blk(16, 16);

    qkv_kernel<<<dim3(1, SEQ / 64, 48), blk>>>(x, wq, wk, wv);

    const size_t shm = 4 * 64 * FST * sizeof(float);  // 69632 B
    cudaFuncSetAttribute(flash_kernel, cudaFuncAttributeMaxDynamicSharedMemorySize, (int)shm);
    flash_kernel<<<dim3(SEQ / 64, NH), blk, shm>>>();

    oproj_kernel<<<dim3(DE / 64, SEQ / 64), blk>>>(wo, out);
}